// round 17
// baseline (speedup 1.0000x reference)
#include <cuda_runtime.h>
#include <cuda_fp16.h>
#include <math.h>

#define BB 32
#define NN 4096
#define DD 256
#define MSGK 256
#define HD 64

// ------------------------- device scratch -------------------------
__device__ int   g_tidx[BB * MSGK];
__device__ float g_tval[BB * MSGK];
__device__ int   g_slot2[BB * NN];
__device__ float g_qkv[BB * MSGK * 3 * DD];
__device__ float g_attn[BB * MSGK * DD];
__device__ float g_msg[BB * MSGK * DD];
__device__ float g_h[(size_t)BB * NN * DD];
__device__ float g_newact[BB * NN];
__device__ float g_dot[2 * BB * NN];

// fp16 2-way splits of weights
__device__ __half g_in0[768*256],  g_in1[768*256];
__device__ __half g_ow0[256*256],  g_ow1[256*256];
__device__ __half g_s10[256*512],  g_s11[256*512];
__device__ __half g_s20[256*256],  g_s21[256*256];
__device__ __half g_a10[256*512],  g_a11[256*512];

// fp16 2-way splits of activations / messages
__device__ __half g_h0[(size_t)BB*NN*DD], g_h1[(size_t)BB*NN*DD];
__device__ __half g_n0[(size_t)BB*NN*DD], g_n1[(size_t)BB*NN*DD];
__device__ __half g_m0[BB*MSGK*DD], g_m1[BB*MSGK*DD];

__device__ __forceinline__ float gelu_f(float x) {
    return 0.5f * x * (1.0f + erff(x * 0.70710678118654752440f));
}

__device__ __forceinline__ unsigned smem_u32(const void* p) {
    unsigned a;
    asm("{ .reg .u64 t; cvta.to.shared.u64 t, %1; cvt.u32.u64 %0, t; }" : "=r"(a) : "l"(p));
    return a;
}

__device__ __forceinline__ void ldsm4(unsigned& r0, unsigned& r1, unsigned& r2, unsigned& r3,
                                      unsigned addr) {
    asm volatile("ldmatrix.sync.aligned.m8n8.x4.shared.b16 {%0,%1,%2,%3}, [%4];"
                 : "=r"(r0), "=r"(r1), "=r"(r2), "=r"(r3) : "r"(addr));
}

__device__ __forceinline__ void mma_f16(float* c, unsigned a0, unsigned a1, unsigned a2,
                                        unsigned a3, unsigned b0, unsigned b1) {
    asm volatile("mma.sync.aligned.m16n8k16.row.col.f32.f16.f16.f32 "
                 "{%0,%1,%2,%3},{%4,%5,%6,%7},{%8,%9},{%0,%1,%2,%3};"
                 : "+f"(c[0]), "+f"(c[1]), "+f"(c[2]), "+f"(c[3])
                 : "r"(a0), "r"(a1), "r"(a2), "r"(a3), "r"(b0), "r"(b1));
}

#define CPASYNC16(dst, src) \
    asm volatile("cp.async.cg.shared.global [%0], [%1], 16;" :: "r"(dst), "l"(src) : "memory")
#define CPCOMMIT() asm volatile("cp.async.commit_group;" ::: "memory")
#define CPWAIT0() asm volatile("cp.async.wait_group 0;" ::: "memory")
#define CPWAIT1() asm volatile("cp.async.wait_group 1;" ::: "memory")

__device__ __forceinline__ unsigned short hbits(__half h) {
    return *(unsigned short*)&h;
}

// ------------------------- merged weight split (fp16 2-way) -------------------
#define SZ_IN  196608
#define SZ_OW  65536
#define SZ_S1  131072
#define SZ_S2  65536
#define SZ_A1  131072
#define SZ_TOT (SZ_IN + SZ_OW + SZ_S1 + SZ_S2 + SZ_A1)

__global__ void split_weights_kernel(
    const float* __restrict__ in_w, const float* __restrict__ out_w,
    const float* __restrict__ su_w1, const float* __restrict__ su_w2,
    const float* __restrict__ au_w1,
    __half* in0, __half* in1, __half* ow0, __half* ow1,
    __half* s10, __half* s11, __half* s20, __half* s21,
    __half* a10, __half* a11) {
    int i = blockIdx.x * 256 + threadIdx.x;
    const float* src; __half *d0, *d1; int off;
    if (i < SZ_IN)                          { src = in_w;  d0 = in0; d1 = in1; off = i; }
    else if (i < SZ_IN+SZ_OW)               { src = out_w; d0 = ow0; d1 = ow1; off = i - SZ_IN; }
    else if (i < SZ_IN+SZ_OW+SZ_S1)         { src = su_w1; d0 = s10; d1 = s11; off = i - SZ_IN - SZ_OW; }
    else if (i < SZ_IN+SZ_OW+SZ_S1+SZ_S2)   { src = su_w2; d0 = s20; d1 = s21; off = i - SZ_IN - SZ_OW - SZ_S1; }
    else if (i < SZ_TOT)                    { src = au_w1; d0 = a10; d1 = a11; off = i - SZ_IN - SZ_OW - SZ_S1 - SZ_S2; }
    else return;
    float v = src[off];
    __half a = __float2half_rn(v);
    d0[off] = a;
    d1[off] = __float2half_rn(v - __half2float(a));
}

// ------------------------- vectorized activation split (x8) -------------------
__global__ void split2v_kernel(const float* __restrict__ W, __half* o0, __half* o1) {
    long long i = ((long long)blockIdx.x * 256 + threadIdx.x) * 8;
    float4 v0 = *(const float4*)(W + i);
    float4 v1 = *(const float4*)(W + i + 4);
    float v[8] = {v0.x, v0.y, v0.z, v0.w, v1.x, v1.y, v1.z, v1.w};
    unsigned short p0[8], p1[8];
#pragma unroll
    for (int j = 0; j < 8; j++) {
        __half a = __float2half_rn(v[j]);
        p0[j] = hbits(a);
        p1[j] = hbits(__float2half_rn(v[j] - __half2float(a)));
    }
    uint4 u0 = make_uint4(((unsigned)p0[1]<<16)|p0[0], ((unsigned)p0[3]<<16)|p0[2],
                          ((unsigned)p0[5]<<16)|p0[4], ((unsigned)p0[7]<<16)|p0[6]);
    uint4 u1 = make_uint4(((unsigned)p1[1]<<16)|p1[0], ((unsigned)p1[3]<<16)|p1[2],
                          ((unsigned)p1[5]<<16)|p1[4], ((unsigned)p1[7]<<16)|p1[6]);
    *(uint4*)(o0 + i) = u0;
    *(uint4*)(o1 + i) = u1;
}

// ------------------------- radix-select top-k (optionally fused act-update) ---
__global__ void radix_topk_kernel(const float* __restrict__ act,
                                  const int* __restrict__ kptr, int kconst,
                                  int* __restrict__ idx_out, float* __restrict__ val_out,
                                  int* __restrict__ slotmap,
                                  const float* __restrict__ dotbuf,
                                  const float* __restrict__ b2,
                                  float* __restrict__ act_out) {
    __shared__ unsigned bits[NN];
    __shared__ unsigned hist[256];
    __shared__ unsigned s_sel[2];
    __shared__ int s_cnt;
    int b = blockIdx.x;
    int tid = threadIdx.x;
    int kk = kptr ? *kptr : kconst;
    if (kk > NN) kk = NN;
    if (kk < 0) kk = 0;

    if (dotbuf) {
        float b2v = b2[0];
        for (int i = tid; i < NN; i += 256) {
            long long g = (long long)b * NN + i;
            float d = dotbuf[g] + dotbuf[(long long)BB * NN + g];
            float dl = 1.0f / (1.0f + expf(-(d + b2v)));
            float na = 0.7f * act[g] + 0.3f * dl;
            na = fminf(fmaxf(na, 0.0f), 1.0f);
            act_out[g] = na;
            bits[i] = __float_as_uint(na);
        }
    } else {
        const float* row = act + (long long)b * NN;
        for (int i = tid; i < NN; i += 256) bits[i] = __float_as_uint(row[i]);
    }

    if (kk == 0) {
        if (slotmap) for (int i = tid; i < NN; i += 256) slotmap[b * NN + i] = -1;
        return;
    }
    __syncthreads();

    unsigned need = (unsigned)kk;
    unsigned prefix = 0;
    unsigned lastE = 0;
    for (int pass = 3; pass >= 0; pass--) {
        hist[tid] = 0;
        __syncthreads();
        int sh = pass * 8;
        for (int i = tid; i < NN; i += 256) {
            unsigned ub = bits[i];
            if ((pass == 3) || ((ub >> (sh + 8)) == prefix))
                atomicAdd(&hist[(ub >> sh) & 255], 1u);
        }
        __syncthreads();
        if (tid == 0) {
            unsigned cum = 0;
            int bsel = 0;
            for (int bin2 = 255; bin2 >= 0; bin2--) {
                unsigned c = hist[bin2];
                if (cum + c >= need) { bsel = bin2; break; }
                cum += c;
            }
            s_sel[0] = (unsigned)bsel;
            s_sel[1] = cum;
        }
        __syncthreads();
        lastE = hist[s_sel[0]];
        need -= s_sel[1];
        prefix = (prefix << 8) | s_sel[0];
        __syncthreads();
    }
    unsigned thr = prefix;
    bool exactAll = (lastE == need);

    if (tid == 0) s_cnt = 0;
    __syncthreads();
    for (int i = tid; i < NN; i += 256) {
        unsigned ub = bits[i];
        bool in = (ub > thr) || (exactAll && ub == thr);
        if (slotmap) slotmap[b * NN + i] = in ? 0 : -1;
        if (in && idx_out) {
            int s = atomicAdd(&s_cnt, 1);
            idx_out[b * kk + s] = i;
            val_out[b * kk + s] = __uint_as_float(ub);
        }
    }
    if (!exactAll) {
        __syncthreads();
        if (tid == 0) {
            int take = (int)need;
            for (int i = 0; i < NN && take > 0; i++) {
                if (bits[i] == thr) {
                    if (slotmap) slotmap[b * NN + i] = 0;
                    if (idx_out) {
                        int s = s_cnt++;
                        idx_out[b * kk + s] = i;
                        val_out[b * kk + s] = __uint_as_float(thr);
                    }
                    take--;
                }
            }
        }
    }
}

// ============ 2-CTA/SM pre-split pipelined tensor GEMM (fp16, 3-term) =========
// CTA tile 128 x 128, 256 threads, 8 warps (4m x 2n), launch_bounds(256,2).
// 3-stage cp.async pipeline (wait_group 1).
// mode 0: bias store. mode 4: bias+gelu+dot(w2) partial -> dotbuf[y][m].
// mode 5: scatter-accumulate into C rows via cgather (no bias).
#define P2_AP 8192
#define P2_BOFF 16384
#define P2_BP 8192
#define P2_STAGE 32768
#define P2_SMEM (3 * P2_STAGE)   // 98304

__global__ __launch_bounds__(256, 2)
void mma_gemm_ps2(const __half* __restrict__ A0, const __half* __restrict__ A1p,
                  const __half* __restrict__ Z0, const __half* __restrict__ Z1,
                  const int* __restrict__ gather, const int* __restrict__ cgather,
                  const __half* __restrict__ W0, const __half* __restrict__ W1, int ldw,
                  const float* __restrict__ bias,
                  const float* __restrict__ w2, float* __restrict__ dotbuf,
                  float* __restrict__ C, int ldc,
                  int K1, int lda1, int lda2, int Ktot, int mode) {
    extern __shared__ char smem[];
    unsigned sbase = smem_u32(smem);
    int tid = threadIdx.x;
    int lane = tid & 31;
    int wid = tid >> 5;
    int wm = wid & 3;
    int wn = wid >> 2;
    int r0 = blockIdx.x * 128;
    int colbase = blockIdx.y * 128;

    // ---- staging maps ----
    int arow = tid >> 1, ahalf = tid & 1;
    int m_a = r0 + arow;
    long long ridx1 = gather ? (long long)((m_a >> 8) * NN + gather[m_a]) : m_a;
    const char* a1b0 = (const char*)(A0 + ridx1 * lda1);
    const char* a1b1 = (const char*)(A1p + ridx1 * lda1);
    const char* a2b0 = Z0 ? (const char*)(Z0 + (long long)m_a * lda2) : a1b0;
    const char* a2b1 = Z1 ? (const char*)(Z1 + (long long)m_a * lda2) : a1b1;
    unsigned aswz = ((arow >> 1) & 3) << 4;
    unsigned ad_a = (unsigned)arow * 64 + (((unsigned)(ahalf * 32)) ^ aswz);
    unsigned ad_b = (unsigned)arow * 64 + (((unsigned)(ahalf * 32 + 16)) ^ aswz);

    long long brow = (long long)(colbase + arow) * ldw;

    const int ta3[3] = {0, 0, 1};
    const int tb3[3] = {0, 1, 0};

    // ---- mma fragment addressing ----
    int a_r = wm * 32 + (lane & 15);
    unsigned a_k0 = (unsigned)((lane >> 4) << 4);
    unsigned a_sw = ((a_r >> 1) & 3) << 4;
    int b_g = lane >> 3, b_r = lane & 7;
    int b_n0 = wn * 64 + ((b_g >> 1) << 3) + b_r;
    unsigned b_k0 = (unsigned)((b_g & 1) << 4);

    float acc[2][8][4];
#pragma unroll
    for (int mt = 0; mt < 2; mt++)
#pragma unroll
        for (int nt = 0; nt < 8; nt++)
#pragma unroll
            for (int c = 0; c < 4; c++) acc[mt][nt][c] = 0.0f;

    int nc = Ktot >> 5;

#define P2_STAGE_FN(c_) do {                                                   \
        int buf_ = (c_) % 3;                                                   \
        unsigned stg_ = sbase + buf_ * P2_STAGE;                               \
        int kc_ = (c_) << 5;                                                   \
        const char *p0_, *p1_; long long ko_;                                  \
        if (kc_ < K1) { p0_ = a1b0; p1_ = a1b1; ko_ = kc_; }                   \
        else          { p0_ = a2b0; p1_ = a2b1; ko_ = kc_ - K1; }              \
        long long ab_ = ko_ * 2 + ahalf * 32;                                  \
        CPASYNC16(stg_ + ad_a, p0_ + ab_);                                     \
        CPASYNC16(stg_ + ad_b, p0_ + ab_ + 16);                                \
        CPASYNC16(stg_ + P2_AP + ad_a, p1_ + ab_);                             \
        CPASYNC16(stg_ + P2_AP + ad_b, p1_ + ab_ + 16);                        \
        long long bo_ = (brow + kc_) * 2 + ahalf * 32;                         \
        unsigned bd_ = stg_ + P2_BOFF;                                         \
        CPASYNC16(bd_ + ad_a, (const char*)W0 + bo_);                          \
        CPASYNC16(bd_ + ad_b, (const char*)W0 + bo_ + 16);                     \
        CPASYNC16(bd_ + P2_BP + ad_a, (const char*)W1 + bo_);                  \
        CPASYNC16(bd_ + P2_BP + ad_b, (const char*)W1 + bo_ + 16);             \
    } while (0)

    P2_STAGE_FN(0);
    CPCOMMIT();
    if (nc > 1) { P2_STAGE_FN(1); CPCOMMIT(); }

    // 3-stage: wait(<=1 outstanding) -> sync -> prefetch c+2 -> mma(c)
    for (int c = 0; c < nc; c++) {
        CPWAIT1();
        __syncthreads();
        if (c + 2 < nc) { P2_STAGE_FN(c + 2); CPCOMMIT(); }

        unsigned stg = sbase + (c % 3) * P2_STAGE;
#pragma unroll
        for (int p = 0; p < 3; p++) {
            unsigned Ab = stg + ta3[p] * P2_AP;
            unsigned Bb = stg + P2_BOFF + tb3[p] * P2_BP;
#pragma unroll
            for (int ks = 0; ks < 2; ks++) {
                unsigned akb = ((unsigned)(ks << 5) + a_k0) ^ a_sw;
                unsigned a0[4], a1r[4];
                ldsm4(a0[0], a0[1], a0[2], a0[3], Ab + (unsigned)a_r * 64 + akb);
                ldsm4(a1r[0], a1r[1], a1r[2], a1r[3], Ab + (unsigned)(a_r + 16) * 64 + akb);
#pragma unroll
                for (int np = 0; np < 4; np++) {
                    int n = b_n0 + np * 16;
                    unsigned bkb = ((unsigned)(ks << 5) + b_k0) ^ (unsigned)(((n >> 1) & 3) << 4);
                    unsigned b0, b1, b2, b3;
                    ldsm4(b0, b1, b2, b3, Bb + (unsigned)n * 64 + bkb);
                    mma_f16(acc[0][2*np],   a0[0], a0[1], a0[2], a0[3], b0, b1);
                    mma_f16(acc[0][2*np+1], a0[0], a0[1], a0[2], a0[3], b2, b3);
                    mma_f16(acc[1][2*np],   a1r[0], a1r[1], a1r[2], a1r[3], b0, b1);
                    mma_f16(acc[1][2*np+1], a1r[0], a1r[1], a1r[2], a1r[3], b2, b3);
                }
            }
        }
    }

    // ---------------- epilogue ----------------
    int qd = lane & 3;
    int rql = lane >> 2;

    if (mode == 5) {
#pragma unroll
        for (int mt = 0; mt < 2; mt++)
#pragma unroll
            for (int hf = 0; hf < 2; hf++) {
                int m = r0 + wm * 32 + mt * 16 + rql + hf * 8;
                long long crow = (long long)((m >> 8) * NN + cgather[m]);
#pragma unroll
                for (int nt = 0; nt < 8; nt++) {
                    int cg = colbase + wn * 64 + nt * 8 + 2 * qd;
                    float* cp = C + crow * ldc + cg;
                    float2 o = *(float2*)cp;
                    o.x += acc[mt][nt][2*hf];
                    o.y += acc[mt][nt][2*hf+1];
                    *(float2*)cp = o;
                }
            }
        return;
    }

    float bv[16];
#pragma unroll
    for (int nt = 0; nt < 8; nt++) {
        int cg = colbase + wn * 64 + nt * 8 + 2 * qd;
        float2 t2 = *(const float2*)(bias + cg);
        bv[2*nt] = t2.x; bv[2*nt+1] = t2.y;
    }

    if (mode == 0) {
#pragma unroll
        for (int mt = 0; mt < 2; mt++)
#pragma unroll
            for (int hf = 0; hf < 2; hf++) {
                int m = r0 + wm * 32 + mt * 16 + rql + hf * 8;
#pragma unroll
                for (int nt = 0; nt < 8; nt++) {
                    int cg = colbase + wn * 64 + nt * 8 + 2 * qd;
                    float2 o;
                    o.x = acc[mt][nt][2*hf]   + bv[2*nt];
                    o.y = acc[mt][nt][2*hf+1] + bv[2*nt+1];
                    *(float2*)(C + (long long)m * ldc + cg) = o;
                }
            }
        return;
    }

    // mode 4: gelu + partial dot over local 128 cols -> dotbuf[y][m]
    {
        __syncthreads();   // smem reuse after last mma reads
        float* red = (float*)smem;
        float wv[16];
#pragma unroll
        for (int nt = 0; nt < 8; nt++) {
            int cg = colbase + wn * 64 + nt * 8 + 2 * qd;
            float2 tw = *(const float2*)(w2 + cg);
            wv[2*nt] = tw.x; wv[2*nt+1] = tw.y;
        }
#pragma unroll
        for (int mt = 0; mt < 2; mt++)
#pragma unroll
            for (int hf = 0; hf < 2; hf++) {
                float d = 0.0f;
#pragma unroll
                for (int nt = 0; nt < 8; nt++) {
                    float f0 = gelu_f(acc[mt][nt][2*hf]   + bv[2*nt]);
                    float f1 = gelu_f(acc[mt][nt][2*hf+1] + bv[2*nt+1]);
                    d += f0 * wv[2*nt] + f1 * wv[2*nt+1];
                }
                d += __shfl_xor_sync(0xffffffffu, d, 1);
                d += __shfl_xor_sync(0xffffffffu, d, 2);
                if (qd == 0) {
                    int rl = wm * 32 + mt * 16 + rql + hf * 8;
                    red[rl * 2 + wn] = d;
                }
            }
        __syncthreads();
        if (tid < 128)
            dotbuf[(long long)blockIdx.y * (BB * NN) + r0 + tid] = red[tid*2] + red[tid*2+1];
    }
}

// ======================= convert-path tensor GEMM (fp32 A, fp16 3-term) =======
#define A_TERM 16384
#define B_TERM 32768
#define BB_OFF (2 * A_TERM)
#define TC_SMEM (2 * A_TERM + 2 * B_TERM)

__global__ __launch_bounds__(512, 1)
void mma_gemm(const float* __restrict__ A1,
              const __half* __restrict__ W0, const __half* __restrict__ W1, int ldw,
              const float* __restrict__ bias,
              const float* __restrict__ rowscale,
              const float* __restrict__ lng, const float* __restrict__ lnb,
              float* __restrict__ C, int ldc,
              __half* __restrict__ n0p, __half* __restrict__ n1p,
              int Ktot, int a1_gelu, int mode) {
    extern __shared__ char smem[];
    unsigned sbase = smem_u32(smem);
    int tid = threadIdx.x;
    int lane = tid & 31;
    int wid = tid >> 5;
    int wm = wid & 3;
    int wn = wid >> 2;
    int r0 = blockIdx.x * 128;
    int colbase = blockIdx.y * 256;

    int s_arow = tid >> 2;
    int s_aq   = tid & 3;
    int m_a = r0 + s_arow;
    const float* a1p = A1 + (long long)m_a * Ktot;

    int s_bn = tid >> 1;
    int s_bh = tid & 1;
    long long bro = (long long)(colbase + s_bn) * ldw;

    const int ta3[3] = {0, 0, 1};
    const int tb3[3] = {0, 1, 0};

    int a_r = wm * 32 + (lane & 15);
    unsigned a_sw = (unsigned)((a_r & 7) << 4);
    unsigned a_kb0 = (unsigned)((lane >> 4) << 4);
    int b_g = lane >> 3, b_r = lane & 7;
    unsigned b_kb0 = (unsigned)((b_g & 1) << 4);

    float acc[2][8][4];
#pragma unroll
    for (int mt = 0; mt < 2; mt++)
#pragma unroll
        for (int nt = 0; nt < 8; nt++)
#pragma unroll
            for (int c = 0; c < 4; c++) acc[mt][nt][c] = 0.0f;

    int nchunks = Ktot >> 6;
    for (int ch = 0; ch < nchunks; ch++) {
        int kc = ch << 6;
        {
            const float* src = a1p + kc + s_aq * 16;
            float v[16];
#pragma unroll
            for (int j = 0; j < 4; j++) {
                float4 t4 = *(const float4*)(src + j * 4);
                v[j*4+0] = t4.x; v[j*4+1] = t4.y; v[j*4+2] = t4.z; v[j*4+3] = t4.w;
            }
            if (a1_gelu) {
#pragma unroll
                for (int j = 0; j < 16; j++) v[j] = gelu_f(v[j]);
            }
            unsigned u0[8], u1[8];
#pragma unroll
            for (int j = 0; j < 8; j++) {
                float x = v[2*j], y = v[2*j+1];
                __half hx0 = __float2half_rn(x);
                __half hy0 = __float2half_rn(y);
                __half hx1 = __float2half_rn(x - __half2float(hx0));
                __half hy1 = __float2half_rn(y - __half2float(hy0));
                u0[j] = ((unsigned)hbits(hy0) << 16) | hbits(hx0);
                u1[j] = ((unsigned)hbits(hy1) << 16) | hbits(hx1);
            }
            unsigned rsw = (unsigned)((s_arow & 7) << 4);
            unsigned rb = (unsigned)s_arow * 128;
#pragma unroll
            for (int j8 = 0; j8 < 4; j8++) {
                unsigned kb = (unsigned)(s_aq * 32 + j8 * 8) ^ rsw;
                *(uint2*)(smem + rb + kb) = make_uint2(u0[2*j8], u0[2*j8+1]);
                *(uint2*)(smem + A_TERM + rb + kb) = make_uint2(u1[2*j8], u1[2*j8+1]);
            }
        }
        {
            unsigned nsw = (unsigned)((s_bn & 7) << 4);
            unsigned nb = (unsigned)s_bn * 128;
            long long goff = (bro + kc) * 2;
#pragma unroll
            for (int w = 0; w < 2; w++) {
                const char* Wsrc = (const char*)((w == 0) ? W0 : W1);
#pragma unroll
                for (int i = 0; i < 4; i++) {
                    unsigned kb = (unsigned)(s_bh * 64 + i * 16);
                    CPASYNC16(sbase + BB_OFF + w * B_TERM + nb + (kb ^ nsw), Wsrc + goff + kb);
                }
            }
        }
        CPCOMMIT();
        CPWAIT0();
        __syncthreads();

#pragma unroll
        for (int p = 0; p < 3; p++) {
            unsigned Ab = sbase + ta3[p] * A_TERM;
            unsigned Bb = sbase + BB_OFF + tb3[p] * B_TERM;
#pragma unroll
            for (int ks = 0; ks < 4; ks++) {
                unsigned a0[4], a1r[4];
                unsigned akb = ((unsigned)(ks * 32) + a_kb0) ^ a_sw;
                ldsm4(a0[0], a0[1], a0[2], a0[3], Ab + (unsigned)a_r * 128 + akb);
                ldsm4(a1r[0], a1r[1], a1r[2], a1r[3], Ab + (unsigned)(a_r + 16) * 128 + akb);
#pragma unroll
                for (int np = 0; np < 4; np++) {
                    int n = wn * 64 + np * 16 + ((b_g >> 1) << 3) + b_r;
                    unsigned bkb = ((unsigned)(ks * 32) + b_kb0) ^ (unsigned)((n & 7) << 4);
                    unsigned b0, b1, b2, b3;
                    ldsm4(b0, b1, b2, b3, Bb + (unsigned)n * 128 + bkb);
                    mma_f16(acc[0][2*np],   a0[0], a0[1], a0[2], a0[3], b0, b1);
                    mma_f16(acc[0][2*np+1], a0[0], a0[1], a0[2], a0[3], b2, b3);
                    mma_f16(acc[1][2*np],   a1r[0], a1r[1], a1r[2], a1r[3], b0, b1);
                    mma_f16(acc[1][2*np+1], a1r[0], a1r[1], a1r[2], a1r[3], b2, b3);
                }
            }
        }
        __syncthreads();
    }

    int qd = lane & 3;
    int rql = lane >> 2;
    float bv[16];
#pragma unroll
    for (int nt = 0; nt < 8; nt++) {
        int cg = colbase + wn * 64 + nt * 8 + 2 * qd;
        float2 t2 = *(const float2*)(bias + cg);
        bv[2*nt] = t2.x; bv[2*nt+1] = t2.y;
    }

    if (mode == 0) {
#pragma unroll
        for (int mt = 0; mt < 2; mt++)
#pragma unroll
            for (int hf = 0; hf < 2; hf++) {
                int m = r0 + wm * 32 + mt * 16 + rql + hf * 8;
                float sc = rowscale ? rowscale[m] : 1.0f;
#pragma unroll
                for (int nt = 0; nt < 8; nt++) {
                    int cg = colbase + wn * 64 + nt * 8 + 2 * qd;
                    float2 o;
                    o.x = (acc[mt][nt][2*hf]   + bv[2*nt])   * sc;
                    o.y = (acc[mt][nt][2*hf+1] + bv[2*nt+1]) * sc;
                    *(float2*)(C + (long long)m * ldc + cg) = o;
                    if (n0p) {
                        long long e = (long long)m * 256 + cg;
                        __half x0 = __float2half_rn(o.x);
                        __half x1 = __float2half_rn(o.x - __half2float(x0));
                        __half y0 = __float2half_rn(o.y);
                        __half y1 = __float2half_rn(o.y - __half2float(y0));
                        *(unsigned*)(n0p + e) = ((unsigned)hbits(y0) << 16) | hbits(x0);
                        *(unsigned*)(n1p + e) = ((unsigned)hbits(y1) << 16) | hbits(x1);
                    }
                }
            }
        return;
    }

    // mode 2: layernorm -> fp16 plane outputs
    float* red = (float*)smem;
    float* red2 = red + 512;
#pragma unroll
    for (int mt = 0; mt < 2; mt++)
#pragma unroll
        for (int hf = 0; hf < 2; hf++) {
            float s = 0.0f, sq = 0.0f;
#pragma unroll
            for (int nt = 0; nt < 8; nt++) {
                float f0 = acc[mt][nt][2*hf]   + bv[2*nt];
                float f1 = acc[mt][nt][2*hf+1] + bv[2*nt+1];
                s += f0 + f1; sq += f0 * f0 + f1 * f1;
            }
            s  += __shfl_xor_sync(0xffffffffu, s, 1);
            s  += __shfl_xor_sync(0xffffffffu, s, 2);
            sq += __shfl_xor_sync(0xffffffffu, sq, 1);
            sq += __shfl_xor_sync(0xffffffffu, sq, 2);
            if (qd == 0) {
                int rl = wm * 32 + mt * 16 + rql + hf * 8;
                red[rl * 4 + wn] = s;
                red2[rl * 4 + wn] = sq;
            }
        }
    __syncthreads();
    float* stats = red2 + 512;
    if (tid < 128) {
        float s = red[tid*4] + red[tid*4+1] + red[tid*4+2] + red[tid*4+3];
        float sq = red2[tid*4] + red2[tid*4+1] + red2[tid*4+2] + red2[tid*4+3];
        float mu = s * (1.0f / 256.0f);
        float var = sq * (1.0f / 256.0f) - mu * mu;
        stats[tid*2] = mu;
        stats[tid*2+1] = rsqrtf(var + 1e-5f);
    }
    __syncthreads();
    float gv[16], ev[16];
#pragma unroll
    for (int nt = 0; nt < 8; nt++) {
        int cg = wn * 64 + nt * 8 + 2 * qd;
        float2 tg = *(const float2*)(lng + cg);
        float2 te = *(const float2*)(lnb + cg);
        gv[2*nt] = tg.x; gv[2*nt+1] = tg.y;
        ev[2*nt] = te.x; ev[2*nt+1] = te.y;
    }
#pragma unroll
    for (int mt = 0; mt < 2; mt++)
#pragma unroll
        for (int hf = 0; hf < 2; hf++) {
            int rl = wm * 32 + mt * 16 + rql + hf * 8;
            int m = r0 + rl;
            float mu = stats[rl*2], inv = stats[rl*2+1];
#pragma unroll
            for (int nt = 0; nt < 8; nt++) {
                int cg = wn * 64 + nt * 8 + 2 * qd;
                float2 o;
                float f0 = acc[mt][nt][2*hf]   + bv[2*nt];
                float f1 = acc[mt][nt][2*hf+1] + bv[2*nt+1];
                o.x = (f0 - mu) * inv * gv[2*nt]   + ev[2*nt];
                o.y = (f1 - mu) * inv * gv[2*nt+1] + ev[2*nt+1];
                if (C) *(float2*)(C + (long long)m * ldc + cg) = o;
                {
                    long long e = (long long)m * 256 + cg;
                    __half x0 = __float2half_rn(o.x);
                    __half x1 = __float2half_rn(o.x - __half2float(x0));
                    __half y0 = __float2half_rn(o.y);
                    __half y1 = __float2half_rn(o.y - __half2float(y0));
                    *(unsigned*)(n0p + e) = ((unsigned)hbits(y0) << 16) | hbits(x0);
                    *(unsigned*)(n1p + e) = ((unsigned)hbits(y1) << 16) | hbits(x1);
                }
            }
        }
}

// ------------------------- attention -------------------------
__global__ void attn_kernel(const float* __restrict__ qkv, float* __restrict__ out) {
    extern __shared__ float sm[];
    float* Ks = sm;
    float* Vs = sm + MSGK * HD;
    int bh = blockIdx.x;
    int b = bh >> 2;
    int h = bh & 3;
    int tid = threadIdx.x;
    const float* base = qkv + (long long)b * MSGK * 768;

    for (int t = tid; t < MSGK * HD; t += 256) {
        int j = t >> 6;
        int d = t & 63;
        Ks[t] = base[j * 768 + 256 + h * 64 + d];
        Vs[t] = base[j * 768 + 512 + h * 64 + d];
    }
    __syncthreads();

    float q[HD], o[HD];
#pragma unroll
    for (int d = 0; d < HD; d++) { q[d] = base[tid * 768 + h * 64 + d] * 0.125f; o[d] = 0.0f; }

    float mval = -1e30f, l = 0.0f;
    for (int j = 0; j < MSGK; j++) {
        float s = 0.0f;
#pragma unroll
        for (int d = 0; d < HD; d++) s += q[d] * Ks[j * 64 + d];
        float nm = fmaxf(mval, s);
        float corr = expf(mval - nm);
        float p = expf(s - nm);
        l = l * corr + p;
#pragma unroll
        for (int d = 0; d < HD; d++) o[d] = o[d] * corr + p * Vs[j * 64 + d];
        mval = nm;
    }
    float inv = 1.0f / l;
    float* op = out + ((long long)(b * MSGK + tid)) * DD + h * 64;
#pragma unroll
    for (int d = 0; d < HD; d++) op[d] = o[d] * inv;
}

// ------------------------- finalize (reconstruct newhid from fp16 planes) ----
__global__ void finalize_kernel(const float* __restrict__ newact,
                                const __half* __restrict__ n0p, const __half* __restrict__ n1p,
                                const int* __restrict__ slot2, float* __restrict__ out) {
    long long total_act = (long long)BB * NN;
    float* out_act = out;
    float* out_hid = out + total_act;
    long long stride = (long long)gridDim.x * blockDim.x;
    long long t0 = (long long)blockIdx.x * blockDim.x + threadIdx.x;

    for (long long i = t0; i < total_act; i += stride)
        out_act[i] = (slot2[i] >= 0) ? newact[i] : 0.0f;

    long long totalh4 = (long long)BB * NN * DD / 4;
    float4* oh4 = reinterpret_cast<float4*>(out_hid);
    for (long long e = t0; e < totalh4; e += stride) {
        long long r = e >> 6;
        if (slot2[r] >= 0) {
            uint2 u0 = *(const uint2*)(n0p + e * 4);
            uint2 u1 = *(const uint2*)(n1p + e * 4);
            float2 a0 = __half22float2(*(const __half2*)&u0.x);
            float2 a1 = __half22float2(*(const __half2*)&u0.y);
            float2 b0 = __half22float2(*(const __half2*)&u1.x);
            float2 b1 = __half22float2(*(const __half2*)&u1.y);
            oh4[e] = make_float4(a0.x + b0.x, a0.y + b0.y, a1.x + b1.x, a1.y + b1.y);
        } else {
            oh4[e] = make_float4(0.f, 0.f, 0.f, 0.f);
        }
    }
}

// ------------------------- host launcher -------------------------
extern "C" void kernel_launch(void* const* d_in, const int* in_sizes, int n_in,
                              void* d_out, int out_size) {
    const float* act    = (const float*)d_in[0];
    const float* hidden = (const float*)d_in[1];
    const float* in_w   = (const float*)d_in[2];
    const float* in_b   = (const float*)d_in[3];
    const float* out_w  = (const float*)d_in[4];
    const float* out_b  = (const float*)d_in[5];
    const float* su_w1  = (const float*)d_in[6];
    const float* su_b1  = (const float*)d_in[7];
    const float* su_w2  = (const float*)d_in[8];
    const float* su_b2  = (const float*)d_in[9];
    const float* au_w1  = (const float*)d_in[10];
    const float* au_b1  = (const float*)d_in[11];
    const float* au_w2  = (const float*)d_in[12];
    const float* au_b2  = (const float*)d_in[13];
    const float* ln_g   = (const float*)d_in[14];
    const float* ln_b   = (const float*)d_in[15];
    const int*   kptr   = (const int*)d_in[16];

    int*   p_tidx;   cudaGetSymbolAddress((void**)&p_tidx,   g_tidx);
    float* p_tval;   cudaGetSymbolAddress((void**)&p_tval,   g_tval);
    int*   p_slot2;  cudaGetSymbolAddress((void**)&p_slot2,  g_slot2);
    float* p_qkv;    cudaGetSymbolAddress((void**)&p_qkv,    g_qkv);
    float* p_attn;   cudaGetSymbolAddress((void**)&p_attn,   g_attn);
    float* p_msg;    cudaGetSymbolAddress((void**)&p_msg,    g_msg);
    float* p_h;      cudaGetSymbolAddress((void**)&p_h,      g_h);
    float* p_newact; cudaGetSymbolAddress((void**)&p_newact, g_newact);
    float* p_dot;    cudaGetSymbolAddress((void**)&p_dot,    g_dot);

    __half *in0,*in1, *ow0,*ow1, *s10,*s11, *s20,*s21, *a10,*a11;
    __half *h0,*h1, *n0,*n1, *m0,*m1;
    cudaGetSymbolAddress((void**)&in0, g_in0); cudaGetSymbolAddress((void**)&in1, g_in1);
    cudaGetSymbolAddress((void**)&ow0, g_ow0); cudaGetSymbolAddress((void**)&ow1, g_ow1);
    cudaGetSymbolAddress((void**)&s10, g_s10); cudaGetSymbolAddress((void**)&s11, g_s11);
    cudaGetSymbolAddress((void**)&s20, g_s20); cudaGetSymbolAddress((void**)&s21, g_s21);
    cudaGetSymbolAddress((void**)&a10, g_a10); cudaGetSymbolAddress((void**)&a11, g_a11);
    cudaGetSymbolAddress((void**)&h0, g_h0); cudaGetSymbolAddress((void**)&h1, g_h1);
    cudaGetSymbolAddress((void**)&n0, g_n0); cudaGetSymbolAddress((void**)&n1, g_n1);
    cudaGetSymbolAddress((void**)&m0, g_m0); cudaGetSymbolAddress((void**)&m1, g_m1);

    const int SMEM_ATTN = 2 * MSGK * HD * 4;

    cudaFuncSetAttribute(mma_gemm, cudaFuncAttributeMaxDynamicSharedMemorySize, TC_SMEM);
    cudaFuncSetAttribute(mma_gemm_ps2, cudaFuncAttributeMaxDynamicSharedMemorySize, P2_SMEM);
    cudaFuncSetAttribute(attn_kernel, cudaFuncAttributeMaxDynamicSharedMemorySize, SMEM_ATTN);

    // side stream + events for graph fork/join
    cudaStream_t s2;
    cudaStreamCreateWithFlags(&s2, cudaStreamNonBlocking);
    cudaEvent_t evF, evS, evJ;
    cudaEventCreateWithFlags(&evF, cudaEventDisableTiming);
    cudaEventCreateWithFlags(&evS, cudaEventDisableTiming);
    cudaEventCreateWithFlags(&evJ, cudaEventDisableTiming);

    // ---- fork: topk1 depends only on `act` ----
    cudaEventRecord(evF, 0);
    cudaStreamWaitEvent(s2, evF, 0);
    radix_topk_kernel<<<BB, 256, 0, s2>>>(act, nullptr, MSGK, p_tidx, p_tval, nullptr,
                                          nullptr, nullptr, nullptr);

    // ---- main: weight + activation prep ----
    split_weights_kernel<<<(SZ_TOT + 255) / 256, 256>>>(
        in_w, out_w, su_w1, su_w2, au_w1,
        in0, in1, ow0, ow1, s10, s11, s20, s21, a10, a11);
    split2v_kernel<<<BB * NN * DD / 2048, 256>>>(hidden, h0, h1);
    cudaEventRecord(evS, 0);

    // ---- side stream: qkv -> attn -> out-proj (+ msg plane emission) ----
    cudaStreamWaitEvent(s2, evS, 0);
    mma_gemm_ps2<<<dim3(64, 6), 256, P2_SMEM, s2>>>(
        h0, h1, nullptr, nullptr, p_tidx, nullptr,
        in0, in1, 256, in_b,
        nullptr, nullptr,
        p_qkv, 768, 256, 256, 256, 256, 0);
    attn_kernel<<<BB * 4, 256, SMEM_ATTN, s2>>>(p_qkv, p_attn);
    mma_gemm<<<dim3(64, 1), 512, TC_SMEM, s2>>>(
        p_attn, ow0, ow1, 256, out_b,
        p_tval, nullptr, nullptr,
        p_msg, 256, m0, m1,
        256, 0, 0);
    cudaEventRecord(evJ, s2);

    // ---- main (concurrent with side stream): su1 dense ----
    mma_gemm_ps2<<<dim3(1024, 2), 256, P2_SMEM>>>(
        h0, h1, nullptr, nullptr, nullptr, nullptr,
        s10, s11, 512, su_b1,
        nullptr, nullptr,
        p_h, 256, 256, 256, 256, 256, 0);

    // ---- join, then serial tail ----
    cudaStreamWaitEvent(0, evJ, 0);

    // su1 sparse: pre[active] += msg @ W1b^T  (ps2 mode 5, scatter-accum)
    // W1b = columns [256,512) of su_w1 -> base s10 + 256 (row-major, ldw=512)
    mma_gemm_ps2<<<dim3(64, 2), 256, P2_SMEM>>>(
        m0, m1, nullptr, nullptr, nullptr, p_tidx,
        s10 + 256, s11 + 256, 512, nullptr,
        nullptr, nullptr,
        p_h, 256, 256, 256, 256, 256, 5);

    // su2: newhid = LN( gelu(pre) @ W2^T + b2 ) -> fp16 planes only
    mma_gemm<<<dim3(1024, 1), 512, TC_SMEM>>>(
        p_h, s20, s21, 256, su_b2,
        nullptr, ln_g, ln_b,
        nullptr, 256, n0, n1,
        256, 1, 2);

    // au1: partial gelu-dot per 128-col half -> g_dot[y][m]
    mma_gemm_ps2<<<dim3(1024, 2), 256, P2_SMEM>>>(
        h0, h1, n0, n1, nullptr, nullptr,
        a10, a11, 512, au_b1,
        au_w2, p_dot,
        nullptr, 256, 256, 256, 256, 512, 4);

    // final top-k fused with act update (k from device sparsity_k)
    radix_topk_kernel<<<BB, 256>>>(act, kptr, 0, nullptr, nullptr, p_slot2,
                                   p_dot, au_b2, p_newact);

    // masked write [sparse_act | sparse_hidden] with fp16-plane reconstruction
    finalize_kernel<<<2048, 256>>>(p_newact, n0, n1, p_slot2, (float*)d_out);
}